// round 2
// baseline (speedup 1.0000x reference)
#include <cuda_runtime.h>
#include <math.h>

#define BQ 131072
#define GEMM_BM 128
#define GEMM_BN 128
#define GEMM_BK 32

// ---------------- scratch (device globals; no allocations) ----------------
__device__ float g_h1[(size_t)4 * BQ * 256];    // expert1 pre-act; later reused as t2_pre [8][BQ][128] (same size)
__device__ float g_fea[(size_t)4 * BQ * 113];   // expert2 pre-act
__device__ float g_task[(size_t)8 * BQ * 113];  // mixed task, [d][b][c]
__device__ float g_t1[(size_t)8 * BQ * 256];    // tower1 pre-act, [d][b][o]
__device__ float g_stats[8][2048];              // per stage: [2s]=sum, [2s+1]=sumsq
__device__ __align__(16) float g_bnA[4][2048];  // folded BN scale per stage
__device__ __align__(16) float g_bnC[4][2048];  // folded BN shift per stage
__device__ int g_domIsI64;

// ---------------- packed fp32x2 FMA helpers (sm_100+) ----------------
__device__ __forceinline__ unsigned long long pack2(float x, float y) {
    unsigned long long d;
    asm("mov.b64 %0, {%1, %2};" : "=l"(d) : "r"(__float_as_uint(x)), "r"(__float_as_uint(y)));
    return d;
}
__device__ __forceinline__ void fma2(unsigned long long& d, unsigned long long a, unsigned long long b) {
    asm("fma.rn.f32x2 %0, %1, %2, %0;" : "+l"(d) : "l"(a), "l"(b));
}

// ---------------- generic sliced GEMM + bias + (optional BN/ReLU pre-op) + stats ----------------
// C[s][b][n] = sum_k f(A[s][b][k]) * W[s][k][n] + bias[s][n];  f(x)=max(a*x+c,0) if PREOP
// Accumulates per-(s,n) sum and sum-of-squares of C into g_stats[2*statStage(+1)].
template<int KDIM, bool PREOP>
__global__ void __launch_bounds__(256, 2) gemm_bn_kernel(
    const float* __restrict__ A, long long aStride,
    const float* __restrict__ W,
    const float* __restrict__ bias,
    int bnStage,
    float* __restrict__ C,
    int statStage, int Btot, int N)
{
    __shared__ float As[GEMM_BK][GEMM_BM + 4];
    __shared__ float Bs[GEMM_BK][GEMM_BN + 4];
    __shared__ float sSum[GEMM_BN], sSq[GEMM_BN];

    const int s  = blockIdx.z;
    const int m0 = blockIdx.x * GEMM_BM;
    const int n0 = blockIdx.y * GEMM_BN;
    const float* Asl = A + (long long)s * aStride;
    const float* Wsl = W + (long long)s * KDIM * N;

    const int tid = threadIdx.x;
    const int tx = tid & 15, ty = tid >> 4;
    const int ka = tid & 31, ra = tid >> 5;
    const int nb = tid & 127, kb = tid >> 7;

    if (tid < GEMM_BN) { sSum[tid] = 0.f; sSq[tid] = 0.f; }

    unsigned long long acc[8][4];
#pragma unroll
    for (int i = 0; i < 8; i++)
#pragma unroll
        for (int j = 0; j < 4; j++) acc[i][j] = pack2(0.f, 0.f);

    for (int k0 = 0; k0 < KDIM; k0 += GEMM_BK) {
        const bool kvalA = (k0 + ka) < KDIM;
        float bna = 0.f, bnc = 0.f;
        if (PREOP && kvalA) {
            bna = g_bnA[bnStage][s * KDIM + k0 + ka];
            bnc = g_bnC[bnStage][s * KDIM + k0 + ka];
        }
#pragma unroll
        for (int i = 0; i < 16; i++) {
            int row = ra + i * 8;
            float v = 0.f;
            if (kvalA) {
                v = Asl[(long long)(m0 + row) * KDIM + (k0 + ka)];
                if (PREOP) v = fmaxf(fmaf(v, bna, bnc), 0.f);
            }
            As[ka][row] = v;
        }
#pragma unroll
        for (int i = 0; i < 16; i++) {
            int kk = kb + i * 2;
            float v = 0.f;
            if ((k0 + kk) < KDIM && (n0 + nb) < N)
                v = Wsl[(long long)(k0 + kk) * N + (n0 + nb)];
            Bs[kk][nb] = v;
        }
        __syncthreads();
#pragma unroll
        for (int k = 0; k < GEMM_BK; k++) {
            float4 a0 = *reinterpret_cast<const float4*>(&As[k][ty * 8]);
            float4 a1 = *reinterpret_cast<const float4*>(&As[k][ty * 8 + 4]);
            ulonglong2 b0 = *reinterpret_cast<const ulonglong2*>(&Bs[k][tx * 8]);
            ulonglong2 b1 = *reinterpret_cast<const ulonglong2*>(&Bs[k][tx * 8 + 4]);
            unsigned long long ad[8];
            ad[0] = pack2(a0.x, a0.x); ad[1] = pack2(a0.y, a0.y);
            ad[2] = pack2(a0.z, a0.z); ad[3] = pack2(a0.w, a0.w);
            ad[4] = pack2(a1.x, a1.x); ad[5] = pack2(a1.y, a1.y);
            ad[6] = pack2(a1.z, a1.z); ad[7] = pack2(a1.w, a1.w);
            unsigned long long bv[4] = { b0.x, b0.y, b1.x, b1.y };
#pragma unroll
            for (int i = 0; i < 8; i++)
#pragma unroll
                for (int j = 0; j < 4; j++) fma2(acc[i][j], ad[i], bv[j]);
        }
        __syncthreads();
    }

    // epilogue: bias, store, per-column stats
    float vals[8][8];
#pragma unroll
    for (int i = 0; i < 8; i++)
#pragma unroll
        for (int j = 0; j < 4; j++) {
            union { unsigned long long u; float2 f; } cv; cv.u = acc[i][j];
            vals[i][2 * j]     = cv.f.x;
            vals[i][2 * j + 1] = cv.f.y;
        }
    float bb[8];
#pragma unroll
    for (int j = 0; j < 8; j++) {
        int col = n0 + tx * 8 + j;
        bb[j] = (col < N) ? bias[(long long)s * N + col] : 0.f;
    }
    float cs[8] = {0,0,0,0,0,0,0,0}, cq[8] = {0,0,0,0,0,0,0,0};
    const bool vec = ((N & 3) == 0);
#pragma unroll
    for (int i = 0; i < 8; i++) {
        long long rb = ((long long)s * Btot + m0 + ty * 8 + i) * N + n0 + tx * 8;
        float v[8];
#pragma unroll
        for (int j = 0; j < 8; j++) {
            v[j] = vals[i][j] + bb[j];
            cs[j] += v[j];
            cq[j] += v[j] * v[j];
        }
        if (vec) {
            *reinterpret_cast<float4*>(&C[rb])     = make_float4(v[0], v[1], v[2], v[3]);
            *reinterpret_cast<float4*>(&C[rb + 4]) = make_float4(v[4], v[5], v[6], v[7]);
        } else {
#pragma unroll
            for (int j = 0; j < 8; j++)
                if (n0 + tx * 8 + j < N) C[rb + j] = v[j];
        }
    }
#pragma unroll
    for (int j = 0; j < 8; j++) {
        int c = tx * 8 + j;
        if (n0 + c < N) {
            atomicAdd(&sSum[c], cs[j]);
            atomicAdd(&sSq[c],  cq[j]);
        }
    }
    __syncthreads();
    if (tid < GEMM_BN) {
        int col = n0 + tid;
        if (col < N) {
            atomicAdd(&g_stats[2 * statStage][s * N + col],     sSum[tid]);
            atomicAdd(&g_stats[2 * statStage + 1][s * N + col], sSq[tid]);
        }
    }
}

// ---------------- small kernels ----------------
__global__ void zero_stats_kernel() {
    int i = blockIdx.x * 1024 + threadIdx.x;
    if (i < 8 * 2048) ((float*)g_stats)[i] = 0.f;
}

__global__ void finalize_kernel(int stage, const float* __restrict__ gamma,
                                const float* __restrict__ beta, int n, float invB) {
    int i = blockIdx.x * blockDim.x + threadIdx.x;
    if (i < n) {
        float m = g_stats[2 * stage][i] * invB;
        float v = g_stats[2 * stage + 1][i] * invB - m * m;
        float sc = gamma[i] / sqrtf(v + 1e-5f);
        g_bnA[stage][i] = sc;
        g_bnC[stage][i] = beta[i] - m * sc;
    }
}

__global__ void probe_domain_kernel(const int* __restrict__ dom) {
    const long long* d64 = (const long long*)dom;
    bool ok = true;
    for (int i = 0; i < 64; i++) {
        long long v = d64[i];
        if (v < 0 || v >= 8) ok = false;
    }
    g_domIsI64 = ok ? 1 : 0;
}

// gates(softmax over E) + BN/ReLU(fea) + expert mixture -> task[d][b][c]
__global__ void gates_task_kernel(const float* __restrict__ emb,
                                  const float* __restrict__ Wg,
                                  const float* __restrict__ bg,
                                  const float* __restrict__ fea_pre,
                                  float* __restrict__ task, int B) {
    __shared__ float s_emb[113];
    __shared__ float s_g[8][4];
    const int b = blockIdx.x;
    const int tid = threadIdx.x;
    if (tid < 113) s_emb[tid] = emb[(long long)b * 113 + tid];
    __syncthreads();
    if (tid < 32) {
        int d = tid >> 2, e = tid & 3;
        float acc = bg[d * 4 + e];
        const float* w = Wg + d * 113 * 4 + e;
        for (int i = 0; i < 113; i++) acc = fmaf(s_emb[i], w[i * 4], acc);
        s_g[d][e] = acc;
    }
    __syncthreads();
    if (tid < 8) {
        float g0 = s_g[tid][0], g1 = s_g[tid][1], g2 = s_g[tid][2], g3 = s_g[tid][3];
        float m = fmaxf(fmaxf(g0, g1), fmaxf(g2, g3));
        float e0 = expf(g0 - m), e1 = expf(g1 - m), e2 = expf(g2 - m), e3 = expf(g3 - m);
        float inv = 1.f / (e0 + e1 + e2 + e3);
        s_g[tid][0] = e0 * inv; s_g[tid][1] = e1 * inv;
        s_g[tid][2] = e2 * inv; s_g[tid][3] = e3 * inv;
    }
    __syncthreads();
    if (tid < 113) {
        float fe[4];
#pragma unroll
        for (int e = 0; e < 4; e++) {
            float x = fea_pre[((long long)e * B + b) * 113 + tid];
            fe[e] = fmaxf(fmaf(x, g_bnA[1][e * 113 + tid], g_bnC[1][e * 113 + tid]), 0.f);
        }
#pragma unroll
        for (int d = 0; d < 8; d++) {
            float t = s_g[d][0] * fe[0] + s_g[d][1] * fe[1] + s_g[d][2] * fe[2] + s_g[d][3] * fe[3];
            task[((long long)d * B + b) * 113 + tid] = t;
        }
    }
}

// final: per b, pick domain tower, BN+ReLU on t2, dot with Wt3, sigmoid
__global__ void final_kernel(const float* __restrict__ t2,
                             const float* __restrict__ Wt3,
                             const float* __restrict__ bt3,
                             const int* __restrict__ dom,
                             float* __restrict__ out, int B) {
    int gid = blockIdx.x * blockDim.x + threadIdx.x;
    int b = gid >> 5, lane = gid & 31;
    if (b >= B) return;
    int d = g_domIsI64 ? (int)(((const long long*)dom)[b]) : dom[b];
    float4 x  = reinterpret_cast<const float4*>(t2 + ((long long)d * B + b) * 128)[lane];
    float4 aa = *reinterpret_cast<const float4*>(&g_bnA[3][d * 128 + lane * 4]);
    float4 cc = *reinterpret_cast<const float4*>(&g_bnC[3][d * 128 + lane * 4]);
    float4 w  = reinterpret_cast<const float4*>(Wt3 + d * 128)[lane];
    float s = fmaxf(fmaf(x.x, aa.x, cc.x), 0.f) * w.x
            + fmaxf(fmaf(x.y, aa.y, cc.y), 0.f) * w.y
            + fmaxf(fmaf(x.z, aa.z, cc.z), 0.f) * w.z
            + fmaxf(fmaf(x.w, aa.w, cc.w), 0.f) * w.w;
#pragma unroll
    for (int o = 16; o; o >>= 1) s += __shfl_xor_sync(0xffffffffu, s, o);
    if (lane == 0) out[b] = 1.f / (1.f + expf(-(s + bt3[d])));
}

// ---------------- host ----------------
extern "C" void kernel_launch(void* const* d_in, const int* in_sizes, int n_in,
                              void* d_out, int out_size) {
    // domain_id is the unique input with exactly B=131072 elements (int dtype).
    const int B = 131072;
    int domIdx = -1;
    for (int i = 0; i < n_in; i++)
        if (in_sizes[i] == B) { domIdx = i; break; }

    const float* ptrs[21];
    int pi = 0;
    for (int i = 0; i < n_in && pi < 21; i++) {
        if (i == domIdx) continue;
        ptrs[pi++] = (const float*)d_in[i];
    }
    // Relative order (identical in both dict order and reference-signature order):
    const float* emb = ptrs[0];
    const float* We1 = ptrs[1],  *be1 = ptrs[2],  *eg1 = ptrs[3],  *eb1 = ptrs[4];
    const float* We2 = ptrs[5],  *be2 = ptrs[6],  *eg2 = ptrs[7],  *eb2 = ptrs[8];
    const float* Wg  = ptrs[9],  *bg  = ptrs[10];
    const float* Wt1 = ptrs[11], *bt1 = ptrs[12], *tg1 = ptrs[13], *tb1 = ptrs[14];
    const float* Wt2 = ptrs[15], *bt2 = ptrs[16], *tg2 = ptrs[17], *tb2 = ptrs[18];
    const float* Wt3 = ptrs[19], *bt3 = ptrs[20];
    const int* dom = (const int*)d_in[domIdx];
    float* out = (float*)d_out;

    float *p_h1, *p_fea, *p_task, *p_t1;
    cudaGetSymbolAddress((void**)&p_h1,  g_h1);
    cudaGetSymbolAddress((void**)&p_fea, g_fea);
    cudaGetSymbolAddress((void**)&p_task, g_task);
    cudaGetSymbolAddress((void**)&p_t1,  g_t1);

    const float invB = 1.f / (float)B;

    probe_domain_kernel<<<1, 1>>>(dom);
    zero_stats_kernel<<<16, 1024>>>();

    // expert layer 1: [B,113] x [113,256] per expert (+stats stage 0)
    gemm_bn_kernel<113, false><<<dim3(B / 128, 2, 4), 256>>>(
        emb, 0LL, We1, be1, 0, p_h1, 0, B, 256);
    finalize_kernel<<<4, 256>>>(0, eg1, eb1, 4 * 256, invB);

    // expert layer 2: BN+ReLU(h1) x [256,113] per expert (+stats stage 1)
    gemm_bn_kernel<256, true><<<dim3(B / 128, 1, 4), 256>>>(
        p_h1, (long long)B * 256, We2, be2, 0, p_fea, 1, B, 113);
    finalize_kernel<<<2, 256>>>(1, eg2, eb2, 4 * 113, invB);

    // gates + mixture -> task[d][b][c]
    gates_task_kernel<<<B, 128>>>(emb, Wg, bg, p_fea, p_task, B);

    // tower layer 1: task x [113,256] per domain (+stats stage 2)
    gemm_bn_kernel<113, false><<<dim3(B / 128, 2, 8), 256>>>(
        p_task, (long long)B * 113, Wt1, bt1, 0, p_t1, 2, B, 256);
    finalize_kernel<<<8, 256>>>(2, tg1, tb1, 8 * 256, invB);

    // tower layer 2: BN+ReLU(t1) x [256,128] per domain (+stats stage 3); output reuses g_h1
    gemm_bn_kernel<256, true><<<dim3(B / 128, 1, 8), 256>>>(
        p_t1, (long long)B * 256, Wt2, bt2, 2, p_h1, 3, B, 128);
    finalize_kernel<<<4, 256>>>(3, tg2, tb2, 8 * 128, invB);

    // final: gather domain, BN+ReLU, dot Wt3, sigmoid
    final_kernel<<<(B * 32) / 256, 256>>>(p_h1, Wt3, bt3, dom, out, B);
}

// round 4
// speedup vs baseline: 1.3548x; 1.3548x over previous
#include <cuda_runtime.h>
#include <math.h>
#include <stdint.h>

#define BQ 131072

// ---------------- scratch (device globals; no allocations) ----------------
__device__ float g_h1[(size_t)4 * BQ * 256];    // expert1 pre-act; later reused as t2_pre [8][BQ][128]
__device__ float g_fea[(size_t)4 * BQ * 128];   // expert2 pre-act, padded stride 128 (113 valid)
__device__ float g_task[(size_t)8 * BQ * 113];  // mixed task, [d][b][c]
__device__ float g_t1[(size_t)8 * BQ * 256];    // tower1 pre-act, [d][b][o]
__device__ float g_stats[8][2048];              // per stage: [2s]=sum, [2s+1]=sumsq
__device__ __align__(16) float g_bnA[4][2048];  // folded BN scale per stage
__device__ __align__(16) float g_bnC[4][2048];  // folded BN shift per stage
__device__ int g_domIsI64;

// ---------------- tf32 mma.sync helpers (sm_80+ PTX, compiles for plain sm_103) ----
__device__ __forceinline__ uint32_t f2tf32(float x) {
    uint32_t r;
    asm("cvt.rna.tf32.f32 %0, %1;" : "=r"(r) : "f"(x));
    return r;
}
__device__ __forceinline__ void mma_tf32(float* c, const uint32_t* a, const uint32_t* b) {
    asm volatile(
        "mma.sync.aligned.m16n8k8.row.col.f32.tf32.tf32.f32 "
        "{%0,%1,%2,%3}, {%4,%5,%6,%7}, {%8,%9}, {%0,%1,%2,%3};"
        : "+f"(c[0]), "+f"(c[1]), "+f"(c[2]), "+f"(c[3])
        : "r"(a[0]), "r"(a[1]), "r"(a[2]), "r"(a[3]), "r"(b[0]), "r"(b[1]));
}

// ---------------- tensor-core GEMM + bias + (optional BN/ReLU pre-op) + stats ----------------
// C[s][b][n0+n] = sum_k f(A[s][b][k]) * W[s][k][n0+n] + bias[s][n0+n]
// Tile M=128, N=128, K-chunk 32. 256 threads, 8 warps (2 x 4), warp tile 64x32.
template<bool PREOP>
__global__ void __launch_bounds__(256, 2) gemm_tc(
    const float* __restrict__ A, long long aSliceStride, int ldA, int KDIM,
    const float* __restrict__ W, int Nw,
    const float* __restrict__ bias, int bnStage,
    float* __restrict__ C, long long cSliceStride, int ldC,
    int Nfeat, int statStage)
{
    __shared__ uint32_t As[128][36];   // [m][k], pad 4 -> conflict-free frag loads
    __shared__ uint32_t Bs[32][136];   // [k][n], pad 8 -> conflict-free frag loads
    __shared__ float sSum[128], sSq[128];

    const int tid = threadIdx.x;
    const int wid = tid >> 5, lane = tid & 31;
    const int wm = wid & 1, wn = wid >> 1;
    const int lr = lane >> 2, lc = lane & 3;

    const int s  = blockIdx.z;
    const int m0 = blockIdx.x * 128;
    const int n0 = blockIdx.y * 128;
    const int nvalid = min(128, Nfeat - n0);

    if (tid < 128) { sSum[tid] = 0.f; sSq[tid] = 0.f; }

    const float* Asl = A + (long long)s * aSliceStride;
    const float* Wsl = W + (long long)s * (long long)KDIM * Nw;

    float acc[4][4][4];
#pragma unroll
    for (int mi = 0; mi < 4; mi++)
#pragma unroll
        for (int ni = 0; ni < 4; ni++)
#pragma unroll
            for (int q = 0; q < 4; q++) acc[mi][ni][q] = 0.f;

    for (int k0 = 0; k0 < KDIM; k0 += 32) {
        // ---- fill A tile (128 x 32), BN/ReLU pre-op fused, cvt to tf32 ----
        {
            const int col = tid & 31;
            const int kg = k0 + col;
            float bna = 0.f, bnc = 0.f;
            const bool kval = kg < KDIM;
            if (PREOP && kval) {
                bna = g_bnA[bnStage][s * KDIM + kg];
                bnc = g_bnC[bnStage][s * KDIM + kg];
            }
#pragma unroll
            for (int i = 0; i < 16; i++) {
                int row = (tid >> 5) + i * 8;
                float v = 0.f;
                if (kval) {
                    v = Asl[(long long)(m0 + row) * ldA + kg];
                    if (PREOP) v = fmaxf(fmaf(v, bna, bnc), 0.f);
                }
                As[row][col] = f2tf32(v);
            }
        }
        // ---- fill B tile (32 x 128) from W[k][n] ----
        {
            const int n = tid & 127;
            const bool nok = n < nvalid;
#pragma unroll
            for (int i = 0; i < 16; i++) {
                int kk = (tid >> 7) + i * 2;
                int kg = k0 + kk;
                float v = 0.f;
                if (kg < KDIM && nok) v = Wsl[(long long)kg * Nw + n0 + n];
                Bs[kk][n] = f2tf32(v);
            }
        }
        __syncthreads();

        // ---- 4 k-steps of m16n8k8 ----
#pragma unroll
        for (int ks = 0; ks < 4; ks++) {
            const int kb = ks * 8;
            uint32_t af[4][4];
#pragma unroll
            for (int mi = 0; mi < 4; mi++) {
                int r = wm * 64 + mi * 16 + lr;
                af[mi][0] = As[r][kb + lc];
                af[mi][1] = As[r + 8][kb + lc];
                af[mi][2] = As[r][kb + 4 + lc];
                af[mi][3] = As[r + 8][kb + 4 + lc];
            }
            uint32_t bf[4][2];
#pragma unroll
            for (int ni = 0; ni < 4; ni++) {
                int cc = wn * 32 + ni * 8 + lr;
                bf[ni][0] = Bs[kb + lc][cc];
                bf[ni][1] = Bs[kb + 4 + lc][cc];
            }
#pragma unroll
            for (int mi = 0; mi < 4; mi++)
#pragma unroll
                for (int ni = 0; ni < 4; ni++)
                    mma_tf32(acc[mi][ni], af[mi], bf[ni]);
        }
        __syncthreads();
    }

    // ---- epilogue: bias, stats, store ----
    float bb[4][2];
#pragma unroll
    for (int ni = 0; ni < 4; ni++) {
        int cl = wn * 32 + ni * 8 + lc * 2;
        bb[ni][0] = (cl < nvalid) ? bias[(long long)s * Nfeat + n0 + cl] : 0.f;
        bb[ni][1] = (cl + 1 < nvalid) ? bias[(long long)s * Nfeat + n0 + cl + 1] : 0.f;
    }
    float cs[4][2] = {{0,0},{0,0},{0,0},{0,0}};
    float cq[4][2] = {{0,0},{0,0},{0,0},{0,0}};

#pragma unroll
    for (int mi = 0; mi < 4; mi++) {
        const int r0 = m0 + wm * 64 + mi * 16 + lr;
#pragma unroll
        for (int ni = 0; ni < 4; ni++) {
            const int cl = wn * 32 + ni * 8 + lc * 2;
            float v00 = acc[mi][ni][0] + bb[ni][0];
            float v01 = acc[mi][ni][1] + bb[ni][1];
            float v10 = acc[mi][ni][2] + bb[ni][0];
            float v11 = acc[mi][ni][3] + bb[ni][1];
            cs[ni][0] += v00 + v10;  cq[ni][0] += v00 * v00 + v10 * v10;
            cs[ni][1] += v01 + v11;  cq[ni][1] += v01 * v01 + v11 * v11;
            float* p0 = C + (long long)s * cSliceStride + (long long)r0 * ldC + n0 + cl;
            float* p1 = p0 + (long long)8 * ldC;
            if (cl + 1 < nvalid) {
                *(float2*)p0 = make_float2(v00, v01);
                *(float2*)p1 = make_float2(v10, v11);
            } else if (cl < nvalid) {
                *p0 = v00;
                *p1 = v10;
            }
        }
    }
#pragma unroll
    for (int ni = 0; ni < 4; ni++)
#pragma unroll
        for (int h = 0; h < 2; h++) {
            int cl = wn * 32 + ni * 8 + lc * 2 + h;
            if (cl < nvalid) {
                atomicAdd(&sSum[cl], cs[ni][h]);
                atomicAdd(&sSq[cl],  cq[ni][h]);
            }
        }
    __syncthreads();
    if (tid < 128 && tid < nvalid) {
        atomicAdd(&g_stats[2 * statStage][s * Nfeat + n0 + tid], sSum[tid]);
        atomicAdd(&g_stats[2 * statStage + 1][s * Nfeat + n0 + tid], sSq[tid]);
    }
}

// ---------------- small kernels ----------------
__global__ void zero_stats_kernel() {
    int i = blockIdx.x * 1024 + threadIdx.x;
    if (i < 8 * 2048) ((float*)g_stats)[i] = 0.f;
}

__global__ void finalize_kernel(int stage, const float* __restrict__ gamma,
                                const float* __restrict__ beta, int n, float invB) {
    int i = blockIdx.x * blockDim.x + threadIdx.x;
    if (i < n) {
        float m = g_stats[2 * stage][i] * invB;
        float v = g_stats[2 * stage + 1][i] * invB - m * m;
        float sc = gamma[i] / sqrtf(v + 1e-5f);
        g_bnA[stage][i] = sc;
        g_bnC[stage][i] = beta[i] - m * sc;
    }
}

__global__ void probe_domain_kernel(const int* __restrict__ dom) {
    const long long* d64 = (const long long*)dom;
    bool ok = true;
    for (int i = 0; i < 64; i++) {
        long long v = d64[i];
        if (v < 0 || v >= 8) ok = false;
    }
    g_domIsI64 = ok ? 1 : 0;
}

// gates(softmax over E) + BN/ReLU(fea) + expert mixture -> task[d][b][c]
__global__ void gates_task_kernel(const float* __restrict__ emb,
                                  const float* __restrict__ Wg,
                                  const float* __restrict__ bg,
                                  const float* __restrict__ fea_pre,
                                  float* __restrict__ task, int B) {
    __shared__ float s_emb[113];
    __shared__ float s_g[8][4];
    const int b = blockIdx.x;
    const int tid = threadIdx.x;
    if (tid < 113) s_emb[tid] = emb[(long long)b * 113 + tid];
    __syncthreads();
    if (tid < 32) {
        int d = tid >> 2, e = tid & 3;
        float acc = bg[d * 4 + e];
        const float* w = Wg + d * 113 * 4 + e;
        for (int i = 0; i < 113; i++) acc = fmaf(s_emb[i], w[i * 4], acc);
        s_g[d][e] = acc;
    }
    __syncthreads();
    if (tid < 8) {
        float g0 = s_g[tid][0], g1 = s_g[tid][1], g2 = s_g[tid][2], g3 = s_g[tid][3];
        float m = fmaxf(fmaxf(g0, g1), fmaxf(g2, g3));
        float e0 = expf(g0 - m), e1 = expf(g1 - m), e2 = expf(g2 - m), e3 = expf(g3 - m);
        float inv = 1.f / (e0 + e1 + e2 + e3);
        s_g[tid][0] = e0 * inv; s_g[tid][1] = e1 * inv;
        s_g[tid][2] = e2 * inv; s_g[tid][3] = e3 * inv;
    }
    __syncthreads();
    if (tid < 113) {
        float fe[4];
#pragma unroll
        for (int e = 0; e < 4; e++) {
            float x = fea_pre[((long long)e * B + b) * 128 + tid];
            fe[e] = fmaxf(fmaf(x, g_bnA[1][e * 113 + tid], g_bnC[1][e * 113 + tid]), 0.f);
        }
#pragma unroll
        for (int d = 0; d < 8; d++) {
            float t = s_g[d][0] * fe[0] + s_g[d][1] * fe[1] + s_g[d][2] * fe[2] + s_g[d][3] * fe[3];
            task[((long long)d * B + b) * 113 + tid] = t;
        }
    }
}

// final: per b, pick domain tower, BN+ReLU on t2, dot with Wt3, sigmoid
__global__ void final_kernel(const float* __restrict__ t2,
                             const float* __restrict__ Wt3,
                             const float* __restrict__ bt3,
                             const int* __restrict__ dom,
                             float* __restrict__ out, int B) {
    int gid = blockIdx.x * blockDim.x + threadIdx.x;
    int b = gid >> 5, lane = gid & 31;
    if (b >= B) return;
    int d = g_domIsI64 ? (int)(((const long long*)dom)[b]) : dom[b];
    float4 x  = reinterpret_cast<const float4*>(t2 + ((long long)d * B + b) * 128)[lane];
    float4 aa = *reinterpret_cast<const float4*>(&g_bnA[3][d * 128 + lane * 4]);
    float4 cc = *reinterpret_cast<const float4*>(&g_bnC[3][d * 128 + lane * 4]);
    float4 w  = reinterpret_cast<const float4*>(Wt3 + d * 128)[lane];
    float s = fmaxf(fmaf(x.x, aa.x, cc.x), 0.f) * w.x
            + fmaxf(fmaf(x.y, aa.y, cc.y), 0.f) * w.y
            + fmaxf(fmaf(x.z, aa.z, cc.z), 0.f) * w.z
            + fmaxf(fmaf(x.w, aa.w, cc.w), 0.f) * w.w;
#pragma unroll
    for (int o = 16; o; o >>= 1) s += __shfl_xor_sync(0xffffffffu, s, o);
    if (lane == 0) out[b] = 1.f / (1.f + expf(-(s + bt3[d])));
}

// ---------------- host ----------------
extern "C" void kernel_launch(void* const* d_in, const int* in_sizes, int n_in,
                              void* d_out, int out_size) {
    const int B = 131072;
    int domIdx = -1;
    for (int i = 0; i < n_in; i++)
        if (in_sizes[i] == B) { domIdx = i; break; }

    const float* ptrs[21];
    int pi = 0;
    for (int i = 0; i < n_in && pi < 21; i++) {
        if (i == domIdx) continue;
        ptrs[pi++] = (const float*)d_in[i];
    }
    const float* emb = ptrs[0];
    const float* We1 = ptrs[1],  *be1 = ptrs[2],  *eg1 = ptrs[3],  *eb1 = ptrs[4];
    const float* We2 = ptrs[5],  *be2 = ptrs[6],  *eg2 = ptrs[7],  *eb2 = ptrs[8];
    const float* Wg  = ptrs[9],  *bg  = ptrs[10];
    const float* Wt1 = ptrs[11], *bt1 = ptrs[12], *tg1 = ptrs[13], *tb1 = ptrs[14];
    const float* Wt2 = ptrs[15], *bt2 = ptrs[16], *tg2 = ptrs[17], *tb2 = ptrs[18];
    const float* Wt3 = ptrs[19], *bt3 = ptrs[20];
    const int* dom = (const int*)d_in[domIdx];
    float* out = (float*)d_out;

    float *p_h1, *p_fea, *p_task, *p_t1;
    cudaGetSymbolAddress((void**)&p_h1,  g_h1);
    cudaGetSymbolAddress((void**)&p_fea, g_fea);
    cudaGetSymbolAddress((void**)&p_task, g_task);
    cudaGetSymbolAddress((void**)&p_t1,  g_t1);

    const float invB = 1.f / (float)B;

    probe_domain_kernel<<<1, 1>>>(dom);
    zero_stats_kernel<<<16, 1024>>>();

    // expert layer 1: emb [B,113] x We1 [113,256] per expert -> h1 (stride 256)
    gemm_tc<false><<<dim3(B / 128, 2, 4), 256>>>(
        emb, 0LL, 113, 113, We1, 256, be1, 0, p_h1, (long long)B * 256, 256, 256, 0);
    finalize_kernel<<<4, 256>>>(0, eg1, eb1, 4 * 256, invB);

    // expert layer 2: BN+ReLU(h1) [B,256] x We2 [256,113] -> fea (stride 128, 113 valid)
    gemm_tc<true><<<dim3(B / 128, 1, 4), 256>>>(
        p_h1, (long long)B * 256, 256, 256, We2, 113, be2, 0, p_fea, (long long)B * 128, 128, 113, 1);
    finalize_kernel<<<2, 256>>>(1, eg2, eb2, 4 * 113, invB);

    // gates + mixture -> task[d][b][c] (stride 113)
    gates_task_kernel<<<B, 128>>>(emb, Wg, bg, p_fea, p_task, B);

    // tower layer 1: task [B,113] x Wt1 [113,256] per domain -> t1 (stride 256)
    gemm_tc<false><<<dim3(B / 128, 2, 8), 256>>>(
        p_task, (long long)B * 113, 113, 113, Wt1, 256, bt1, 0, p_t1, (long long)B * 256, 256, 256, 2);
    finalize_kernel<<<8, 256>>>(2, tg1, tb1, 8 * 256, invB);

    // tower layer 2: BN+ReLU(t1) [B,256] x Wt2 [256,128] per domain -> t2 (reuses g_h1, stride 128)
    gemm_tc<true><<<dim3(B / 128, 1, 8), 256>>>(
        p_t1, (long long)B * 256, 256, 256, Wt2, 128, bt2, 2, p_h1, (long long)B * 128, 128, 128, 3);
    finalize_kernel<<<4, 256>>>(3, tg2, tb2, 8 * 128, invB);

    // final: gather domain, BN+ReLU, dot Wt3, sigmoid
    final_kernel<<<(B * 32) / 256, 256>>>(p_h1, Wt3, bt3, dom, out, B);
}

// round 6
// speedup vs baseline: 1.8643x; 1.3761x over previous
#include <cuda_runtime.h>
#include <math.h>
#include <stdint.h>

#define BQ 131072

// ---------------- scratch (device globals; no allocations) ----------------
__device__ float g_h1[(size_t)4 * BQ * 256];    // expert1 pre-act; later reused as t2_pre [8][BQ][128]
__device__ float g_fea[(size_t)4 * BQ * 128];   // expert2 pre-act, stride 128 (113 valid)
__device__ float g_task[(size_t)8 * BQ * 128];  // mixed task, [d][b][c], stride 128 (113 valid, pad zeroed)
__device__ float g_t1[(size_t)8 * BQ * 256];    // tower1 pre-act, [d][b][o]
__device__ float g_stats[8][2048];              // per stage: [2s]=sum, [2s+1]=sumsq
__device__ __align__(16) float g_bnA[4][2048];  // folded BN scale per stage
__device__ __align__(16) float g_bnC[4][2048];  // folded BN shift per stage
__device__ int g_domIsI64;

// ---------------- tf32 mma.sync helpers ----------------
__device__ __forceinline__ uint32_t f2tf32(float x) {
    uint32_t r;
    asm("cvt.rna.tf32.f32 %0, %1;" : "=r"(r) : "f"(x));
    return r;
}
__device__ __forceinline__ void mma_tf32(float* c, const uint32_t* a, const uint32_t* b) {
    asm volatile(
        "mma.sync.aligned.m16n8k8.row.col.f32.tf32.tf32.f32 "
        "{%0,%1,%2,%3}, {%4,%5,%6,%7}, {%8,%9}, {%0,%1,%2,%3};"
        : "+f"(c[0]), "+f"(c[1]), "+f"(c[2]), "+f"(c[3])
        : "r"(a[0]), "r"(a[1]), "r"(a[2]), "r"(a[3]), "r"(b[0]), "r"(b[1]));
}
__device__ __forceinline__ uint32_t smem_addr(const void* p) {
    return (uint32_t)__cvta_generic_to_shared(p);
}

// smem word offsets
#define AS_WORDS (2 * 128 * 36)
#define BS_WORDS (2 * 32 * 136)
#define SMEM_BYTES ((AS_WORDS + BS_WORDS + 256 + 512) * 4)

// ---------------- double-buffered tf32 GEMM + bias + optional BN/ReLU pre-op + BN stats ----
// C[s][b][n0+n] = sum_k f(A[s][b][k]) * W[s][k][n0+n] + bias[s][n0+n]
// Tile M=128, N=128, K-chunk 32, 256 threads (8 warps, warp tile 64x32).
template<bool AVEC, bool BVEC, bool PREOP, int MINB>
__global__ void __launch_bounds__(256, MINB) gemm_tc(
    const float* __restrict__ A, long long aSliceStride, int ldA, int KDIM, int aKmax,
    const float* __restrict__ W, int Nw,
    const float* __restrict__ bias, int bnStage,
    float* __restrict__ C, long long cSliceStride, int ldC,
    int Nfeat, int statStage)
{
    extern __shared__ char dsm[];
    uint32_t* smw = (uint32_t*)dsm;
    // As[2][128][36], Bs[2][32][136], sBNa[256], sBNc[256], sSum[128], sSq[128]
    uint32_t (*As)[128][36] = (uint32_t(*)[128][36])smw;
    uint32_t (*Bs)[32][136] = (uint32_t(*)[32][136])(smw + AS_WORDS);
    float* sBNa = (float*)(smw + AS_WORDS + BS_WORDS);
    float* sBNc = sBNa + 256;   // KDIM <= 256 for PREOP stages (FIXED: was +128 -> write race)
    float* sSum = (float*)(smw + AS_WORDS + BS_WORDS + 512);
    float* sSq  = sSum + 128;

    const int tid = threadIdx.x;
    const int wid = tid >> 5, lane = tid & 31;
    const int wm = wid & 1, wn = wid >> 1;
    const int lr = lane >> 2, lc = lane & 3;

    const int s  = blockIdx.z;
    const int m0 = blockIdx.x * 128;
    const int n0 = blockIdx.y * 128;
    const int nvalid = min(128, Nfeat - n0);
    const int NC = (KDIM + 31) >> 5;

    const float* Asl = A + (long long)s * aSliceStride;
    const float* Wsl = W + (long long)s * (long long)KDIM * Nw;

    if (tid < 128) { sSum[tid] = 0.f; sSq[tid] = 0.f; }
    if (PREOP) {
        for (int i = tid; i < KDIM; i += 256) {
            sBNa[i] = g_bnA[bnStage][s * KDIM + i];
            sBNc[i] = g_bnC[bnStage][s * KDIM + i];
        }
    }

    float4 aReg[4];     // AVEC prefetch
    float  aS[16];      // scalar A prefetch
    float  bS[16];      // scalar B prefetch

    // ---- prefetch A for chunk c into registers ----
    auto prefA = [&](int c) {
        const int k0 = c * 32;
        if (AVEC) {
#pragma unroll
            for (int p = 0; p < 4; p++) {
                int f = tid + p * 256;
                int row = f >> 3, q = f & 7;
                int kg = k0 + q * 4;
                if (kg < aKmax)
                    aReg[p] = *(const float4*)(Asl + (long long)(m0 + row) * ldA + kg);
                else
                    aReg[p] = make_float4(0.f, 0.f, 0.f, 0.f);
            }
        } else {
            const int col = tid & 31;
            const int kg = k0 + col;
            const bool kval = kg < KDIM;
#pragma unroll
            for (int i = 0; i < 16; i++) {
                int row = (tid >> 5) + i * 8;
                aS[i] = kval ? Asl[(long long)(m0 + row) * ldA + kg] : 0.f;
            }
        }
    };
    // ---- store prefetched A into smem buffer (with preop + tf32 cvt) ----
    auto stsA = [&](int buf, int c) {
        const int k0 = c * 32;
        if (AVEC) {
#pragma unroll
            for (int p = 0; p < 4; p++) {
                int f = tid + p * 256;
                int row = f >> 3, q = f & 7;
                float4 v = aReg[p];
                if (PREOP) {
                    int kb = k0 + q * 4;
                    float4 a4 = *(const float4*)&sBNa[kb];
                    float4 c4 = *(const float4*)&sBNc[kb];
                    v.x = fmaxf(fmaf(v.x, a4.x, c4.x), 0.f);
                    v.y = fmaxf(fmaf(v.y, a4.y, c4.y), 0.f);
                    v.z = fmaxf(fmaf(v.z, a4.z, c4.z), 0.f);
                    v.w = fmaxf(fmaf(v.w, a4.w, c4.w), 0.f);
                }
                uint4 t;
                t.x = f2tf32(v.x); t.y = f2tf32(v.y);
                t.z = f2tf32(v.z); t.w = f2tf32(v.w);
                *(uint4*)&As[buf][row][q * 4] = t;
            }
        } else {
            const int col = tid & 31;
#pragma unroll
            for (int i = 0; i < 16; i++) {
                int row = (tid >> 5) + i * 8;
                As[buf][row][col] = f2tf32(aS[i]);
            }
        }
    };
    // ---- prefetch B for chunk c: cp.async straight into buffer (BVEC) or registers ----
    auto prefB = [&](int c, int buf) {
        const int k0 = c * 32;
        if (BVEC) {
#pragma unroll
            for (int i = 0; i < 4; i++) {
                int kk = (tid >> 5) + i * 8;
                int n4 = (tid & 31) * 4;
                int kg = k0 + kk;
                int rem = nvalid - n4;
                int bytes = (kg < KDIM) ? min(max(rem, 0) * 4, 16) : 0;
                const float* src = Wsl + ((bytes > 0) ? ((long long)kg * Nw + n0 + n4) : 0LL);
                uint32_t dst = smem_addr(&Bs[buf][kk][n4]);
                asm volatile("cp.async.ca.shared.global [%0], [%1], 16, %2;"
                             :: "r"(dst), "l"(src), "r"(bytes) : "memory");
            }
            asm volatile("cp.async.commit_group;" ::: "memory");
        } else {
            const int n = tid & 127;
            const bool nok = n < nvalid;
#pragma unroll
            for (int i = 0; i < 16; i++) {
                int kk = (tid >> 7) + i * 2;
                int kg = k0 + kk;
                bS[i] = (kg < KDIM && nok) ? Wsl[(long long)kg * Nw + n0 + n] : 0.f;
            }
        }
    };
    auto stsB = [&](int buf) {
        if (!BVEC) {
            const int n = tid & 127;
#pragma unroll
            for (int i = 0; i < 16; i++) {
                int kk = (tid >> 7) + i * 2;
                Bs[buf][kk][n] = __float_as_uint(bS[i]);
            }
        }
    };

    float acc[4][4][4];
#pragma unroll
    for (int mi = 0; mi < 4; mi++)
#pragma unroll
        for (int ni = 0; ni < 4; ni++)
#pragma unroll
            for (int q = 0; q < 4; q++) acc[mi][ni][q] = 0.f;

    // ---- prologue: fill buffer 0 ----
    prefA(0);
    prefB(0, 0);
    if (PREOP) __syncthreads();   // sBN ready before stsA uses it
    stsA(0, 0);
    stsB(0);
    if (BVEC) asm volatile("cp.async.wait_group 0;" ::: "memory");
    __syncthreads();

    // ---- main pipeline ----
    for (int c = 0; c < NC; c++) {
        const int cur = c & 1;
        const bool more = (c + 1) < NC;
        if (more) { prefA(c + 1); prefB(c + 1, cur ^ 1); }

        uint32_t (*Ab)[36] = As[cur];
        uint32_t (*Bb)[136] = Bs[cur];
#pragma unroll
        for (int ks = 0; ks < 4; ks++) {
            const int kb = ks * 8;
            uint32_t af[4][4];
#pragma unroll
            for (int mi = 0; mi < 4; mi++) {
                int r = wm * 64 + mi * 16 + lr;
                af[mi][0] = Ab[r][kb + lc];
                af[mi][1] = Ab[r + 8][kb + lc];
                af[mi][2] = Ab[r][kb + 4 + lc];
                af[mi][3] = Ab[r + 8][kb + 4 + lc];
            }
            uint32_t bf[4][2];
#pragma unroll
            for (int ni = 0; ni < 4; ni++) {
                int cc = wn * 32 + ni * 8 + lr;
                bf[ni][0] = Bb[kb + lc][cc];
                bf[ni][1] = Bb[kb + 4 + lc][cc];
            }
#pragma unroll
            for (int mi = 0; mi < 4; mi++)
#pragma unroll
                for (int ni = 0; ni < 4; ni++)
                    mma_tf32(acc[mi][ni], af[mi], bf[ni]);
        }

        if (more) { stsA(cur ^ 1, c + 1); stsB(cur ^ 1); }
        if (BVEC) asm volatile("cp.async.wait_group 0;" ::: "memory");
        __syncthreads();
    }

    // ---- epilogue: bias, stats, store ----
    float bb[4][2];
#pragma unroll
    for (int ni = 0; ni < 4; ni++) {
        int cl = wn * 32 + ni * 8 + lc * 2;
        bb[ni][0] = (cl < nvalid) ? bias[(long long)s * Nfeat + n0 + cl] : 0.f;
        bb[ni][1] = (cl + 1 < nvalid) ? bias[(long long)s * Nfeat + n0 + cl + 1] : 0.f;
    }
    float cs[4][2] = {{0,0},{0,0},{0,0},{0,0}};
    float cq[4][2] = {{0,0},{0,0},{0,0},{0,0}};

#pragma unroll
    for (int mi = 0; mi < 4; mi++) {
        const int r0 = m0 + wm * 64 + mi * 16 + lr;
#pragma unroll
        for (int ni = 0; ni < 4; ni++) {
            const int cl = wn * 32 + ni * 8 + lc * 2;
            float v00 = acc[mi][ni][0] + bb[ni][0];
            float v01 = acc[mi][ni][1] + bb[ni][1];
            float v10 = acc[mi][ni][2] + bb[ni][0];
            float v11 = acc[mi][ni][3] + bb[ni][1];
            cs[ni][0] += v00 + v10;  cq[ni][0] += v00 * v00 + v10 * v10;
            cs[ni][1] += v01 + v11;  cq[ni][1] += v01 * v01 + v11 * v11;
            float* p0 = C + (long long)s * cSliceStride + (long long)r0 * ldC + n0 + cl;
            float* p1 = p0 + (long long)8 * ldC;
            if (cl + 1 < nvalid) {
                *(float2*)p0 = make_float2(v00, v01);
                *(float2*)p1 = make_float2(v10, v11);
            } else if (cl < nvalid) {
                *p0 = v00;
                *p1 = v10;
            }
        }
    }
#pragma unroll
    for (int ni = 0; ni < 4; ni++)
#pragma unroll
        for (int h = 0; h < 2; h++) {
            int cl = wn * 32 + ni * 8 + lc * 2 + h;
            if (cl < nvalid) {
                atomicAdd(&sSum[cl], cs[ni][h]);
                atomicAdd(&sSq[cl],  cq[ni][h]);
            }
        }
    __syncthreads();
    if (tid < 128 && tid < nvalid) {
        atomicAdd(&g_stats[2 * statStage][s * Nfeat + n0 + tid], sSum[tid]);
        atomicAdd(&g_stats[2 * statStage + 1][s * Nfeat + n0 + tid], sSq[tid]);
    }
}

// ---------------- small kernels ----------------
__global__ void zero_stats_kernel() {
    int i = blockIdx.x * 1024 + threadIdx.x;
    if (i < 8 * 2048) ((float*)g_stats)[i] = 0.f;
}

__global__ void finalize_kernel(int stage, const float* __restrict__ gamma,
                                const float* __restrict__ beta, int n, float invB) {
    int i = blockIdx.x * blockDim.x + threadIdx.x;
    if (i < n) {
        float m = g_stats[2 * stage][i] * invB;
        float v = g_stats[2 * stage + 1][i] * invB - m * m;
        float sc = gamma[i] / sqrtf(v + 1e-5f);
        g_bnA[stage][i] = sc;
        g_bnC[stage][i] = beta[i] - m * sc;
    }
}

__global__ void probe_domain_kernel(const int* __restrict__ dom) {
    const long long* d64 = (const long long*)dom;
    bool ok = true;
    for (int i = 0; i < 64; i++) {
        long long v = d64[i];
        if (v < 0 || v >= 8) ok = false;
    }
    g_domIsI64 = ok ? 1 : 0;
}

// gates(softmax over E) + BN/ReLU(fea) + expert mixture -> task[d][b][c] (stride 128, pad zeroed)
__global__ void gates_task_kernel(const float* __restrict__ emb,
                                  const float* __restrict__ Wg,
                                  const float* __restrict__ bg,
                                  const float* __restrict__ fea_pre,
                                  float* __restrict__ task, int B) {
    __shared__ float s_emb[113];
    __shared__ float s_g[8][4];
    const int b = blockIdx.x;
    const int tid = threadIdx.x;
    if (tid < 113) s_emb[tid] = emb[(long long)b * 113 + tid];
    __syncthreads();
    if (tid < 32) {
        int d = tid >> 2, e = tid & 3;
        float acc = bg[d * 4 + e];
        const float* w = Wg + d * 113 * 4 + e;
        for (int i = 0; i < 113; i++) acc = fmaf(s_emb[i], w[i * 4], acc);
        s_g[d][e] = acc;
    }
    __syncthreads();
    if (tid < 8) {
        float g0 = s_g[tid][0], g1 = s_g[tid][1], g2 = s_g[tid][2], g3 = s_g[tid][3];
        float m = fmaxf(fmaxf(g0, g1), fmaxf(g2, g3));
        float e0 = expf(g0 - m), e1 = expf(g1 - m), e2 = expf(g2 - m), e3 = expf(g3 - m);
        float inv = 1.f / (e0 + e1 + e2 + e3);
        s_g[tid][0] = e0 * inv; s_g[tid][1] = e1 * inv;
        s_g[tid][2] = e2 * inv; s_g[tid][3] = e3 * inv;
    }
    __syncthreads();
    if (tid < 113) {
        float fe[4];
#pragma unroll
        for (int e = 0; e < 4; e++) {
            float x = fea_pre[((long long)e * B + b) * 128 + tid];
            fe[e] = fmaxf(fmaf(x, g_bnA[1][e * 113 + tid], g_bnC[1][e * 113 + tid]), 0.f);
        }
#pragma unroll
        for (int d = 0; d < 8; d++) {
            float t = s_g[d][0] * fe[0] + s_g[d][1] * fe[1] + s_g[d][2] * fe[2] + s_g[d][3] * fe[3];
            task[((long long)d * B + b) * 128 + tid] = t;
        }
    } else {
        // zero the pad columns 113..127 so tower1's vector A loads read zeros
#pragma unroll
        for (int d = 0; d < 8; d++)
            task[((long long)d * B + b) * 128 + tid] = 0.f;
    }
}

// final: per b, pick domain tower, BN+ReLU on t2, dot with Wt3, sigmoid
__global__ void final_kernel(const float* __restrict__ t2,
                             const float* __restrict__ Wt3,
                             const float* __restrict__ bt3,
                             const int* __restrict__ dom,
                             float* __restrict__ out, int B) {
    int gid = blockIdx.x * blockDim.x + threadIdx.x;
    int b = gid >> 5, lane = gid & 31;
    if (b >= B) return;
    int d = g_domIsI64 ? (int)(((const long long*)dom)[b]) : dom[b];
    float4 x  = reinterpret_cast<const float4*>(t2 + ((long long)d * B + b) * 128)[lane];
    float4 aa = *reinterpret_cast<const float4*>(&g_bnA[3][d * 128 + lane * 4]);
    float4 cc = *reinterpret_cast<const float4*>(&g_bnC[3][d * 128 + lane * 4]);
    float4 w  = reinterpret_cast<const float4*>(Wt3 + d * 128)[lane];
    float s = fmaxf(fmaf(x.x, aa.x, cc.x), 0.f) * w.x
            + fmaxf(fmaf(x.y, aa.y, cc.y), 0.f) * w.y
            + fmaxf(fmaf(x.z, aa.z, cc.z), 0.f) * w.z
            + fmaxf(fmaf(x.w, aa.w, cc.w), 0.f) * w.w;
#pragma unroll
    for (int o = 16; o; o >>= 1) s += __shfl_xor_sync(0xffffffffu, s, o);
    if (lane == 0) out[b] = 1.f / (1.f + expf(-(s + bt3[d])));
}

// ---------------- host ----------------
extern "C" void kernel_launch(void* const* d_in, const int* in_sizes, int n_in,
                              void* d_out, int out_size) {
    const int B = 131072;
    int domIdx = -1;
    for (int i = 0; i < n_in; i++)
        if (in_sizes[i] == B) { domIdx = i; break; }

    const float* ptrs[21];
    int pi = 0;
    for (int i = 0; i < n_in && pi < 21; i++) {
        if (i == domIdx) continue;
        ptrs[pi++] = (const float*)d_in[i];
    }
    const float* emb = ptrs[0];
    const float* We1 = ptrs[1],  *be1 = ptrs[2],  *eg1 = ptrs[3],  *eb1 = ptrs[4];
    const float* We2 = ptrs[5],  *be2 = ptrs[6],  *eg2 = ptrs[7],  *eb2 = ptrs[8];
    const float* Wg  = ptrs[9],  *bg  = ptrs[10];
    const float* Wt1 = ptrs[11], *bt1 = ptrs[12], *tg1 = ptrs[13], *tb1 = ptrs[14];
    const float* Wt2 = ptrs[15], *bt2 = ptrs[16], *tg2 = ptrs[17], *tb2 = ptrs[18];
    const float* Wt3 = ptrs[19], *bt3 = ptrs[20];
    const int* dom = (const int*)d_in[domIdx];
    float* out = (float*)d_out;

    float *p_h1, *p_fea, *p_task, *p_t1;
    cudaGetSymbolAddress((void**)&p_h1,  g_h1);
    cudaGetSymbolAddress((void**)&p_fea, g_fea);
    cudaGetSymbolAddress((void**)&p_task, g_task);
    cudaGetSymbolAddress((void**)&p_t1,  g_t1);

    cudaFuncSetAttribute(gemm_tc<false, true,  false, 2>, cudaFuncAttributeMaxDynamicSharedMemorySize, SMEM_BYTES);
    cudaFuncSetAttribute(gemm_tc<true,  false, true,  1>, cudaFuncAttributeMaxDynamicSharedMemorySize, SMEM_BYTES);
    cudaFuncSetAttribute(gemm_tc<true,  true,  false, 2>, cudaFuncAttributeMaxDynamicSharedMemorySize, SMEM_BYTES);
    cudaFuncSetAttribute(gemm_tc<true,  true,  true,  2>, cudaFuncAttributeMaxDynamicSharedMemorySize, SMEM_BYTES);

    const float invB = 1.f / (float)B;

    probe_domain_kernel<<<1, 1>>>(dom);
    zero_stats_kernel<<<16, 1024>>>();

    // expert layer 1: emb [B,113] x We1 [113,256] per expert -> h1 (stride 256)
    gemm_tc<false, true, false, 2><<<dim3(B / 128, 2, 4), 256, SMEM_BYTES>>>(
        emb, 0LL, 113, 113, 113, We1, 256, be1, 0, p_h1, (long long)B * 256, 256, 256, 0);
    finalize_kernel<<<4, 256>>>(0, eg1, eb1, 4 * 256, invB);

    // expert layer 2: BN+ReLU(h1) [B,256] x We2 [256,113] -> fea (stride 128, 113 valid)
    gemm_tc<true, false, true, 1><<<dim3(B / 128, 1, 4), 256, SMEM_BYTES>>>(
        p_h1, (long long)B * 256, 256, 256, 256, We2, 113, be2, 0, p_fea, (long long)B * 128, 128, 113, 1);
    finalize_kernel<<<2, 256>>>(1, eg2, eb2, 4 * 113, invB);

    // gates + mixture -> task[d][b][c] (stride 128, pad zeroed)
    gates_task_kernel<<<B, 128>>>(emb, Wg, bg, p_fea, p_task, B);

    // tower layer 1: task [B,113 pad 128] x Wt1 [113,256] per domain -> t1 (stride 256)
    gemm_tc<true, true, false, 2><<<dim3(B / 128, 2, 8), 256, SMEM_BYTES>>>(
        p_task, (long long)B * 128, 128, 113, 128, Wt1, 256, bt1, 0, p_t1, (long long)B * 256, 256, 256, 2);
    finalize_kernel<<<8, 256>>>(2, tg1, tb1, 8 * 256, invB);

    // tower layer 2: BN+ReLU(t1) [B,256] x Wt2 [256,128] per domain -> t2 (reuses g_h1, stride 128)
    gemm_tc<true, true, true, 2><<<dim3(B / 128, 1, 8), 256, SMEM_BYTES>>>(
        p_t1, (long long)B * 256, 256, 256, 256, Wt2, 128, bt2, 2, p_h1, (long long)B * 128, 128, 128, 3);
    finalize_kernel<<<4, 256>>>(3, tg2, tb2, 8 * 128, invB);

    // final: gather domain, BN+ReLU, dot Wt3, sigmoid
    final_kernel<<<(B * 32) / 256, 256>>>(p_h1, Wt3, bt3, dom, out, B);
}

// round 7
// speedup vs baseline: 1.8694x; 1.0027x over previous
#include <cuda_runtime.h>
#include <math.h>
#include <stdint.h>

#define BQ 131072

// ---------------- scratch (device globals; no allocations) ----------------
__device__ float g_h1[(size_t)4 * BQ * 256];    // expert1 pre-act; later reused as t2_pre [8][BQ][128]
__device__ float g_fea[(size_t)4 * BQ * 128];   // expert2 pre-act, stride 128 (113 valid)
__device__ float g_task[(size_t)8 * BQ * 128];  // mixed task, [d][b][c], stride 128 (113 valid, pad zeroed)
__device__ float g_t1[(size_t)8 * BQ * 256];    // tower1 pre-act, [d][b][o]
__device__ float g_stats[8][2048];              // per stage: [2s]=sum, [2s+1]=sumsq
__device__ __align__(16) float g_bnA[4][2048];  // folded BN scale per stage
__device__ __align__(16) float g_bnC[4][2048];  // folded BN shift per stage
__device__ int g_domIsI64;

// ---------------- tf32 mma.sync helpers ----------------
__device__ __forceinline__ uint32_t f2tf32(float x) {
    uint32_t r;
    asm("cvt.rna.tf32.f32 %0, %1;" : "=r"(r) : "f"(x));
    return r;
}
__device__ __forceinline__ void mma_tf32(float* c, const uint32_t* a, const uint32_t* b) {
    asm volatile(
        "mma.sync.aligned.m16n8k8.row.col.f32.tf32.tf32.f32 "
        "{%0,%1,%2,%3}, {%4,%5,%6,%7}, {%8,%9}, {%0,%1,%2,%3};"
        : "+f"(c[0]), "+f"(c[1]), "+f"(c[2]), "+f"(c[3])
        : "r"(a[0]), "r"(a[1]), "r"(a[2]), "r"(a[3]), "r"(b[0]), "r"(b[1]));
}
__device__ __forceinline__ uint32_t smem_addr(const void* p) {
    return (uint32_t)__cvta_generic_to_shared(p);
}

// ======================================================================
// gemm_async: fully cp.async staged GEMM (no pre-op), 3-deep pipeline.
// A must be 16B-aligned rows with ldA = 128, KDIM = 128 (pad cols zeroed).
// C[s][m][n0+n] = sum_k A[s][m][k] * W[s][k][n] + bias[s][n], + BN stats.
// Grid: x = n-tile, y = m-tile, z = slice. 256 threads.
// ======================================================================
#define ASY_WORDS (3 * 128 * 36 + 3 * 32 * 136 + 256)
#define ASY_BYTES (ASY_WORDS * 4)

__global__ void __launch_bounds__(256, 2) gemm_async(
    const float* __restrict__ A, long long aSliceStride,
    const float* __restrict__ W, int Nw, int KB,
    const float* __restrict__ bias,
    float* __restrict__ C, long long cSliceStride, int ldC,
    int Nfeat, int statStage)
{
    extern __shared__ char dsm[];
    uint32_t* smw = (uint32_t*)dsm;
    uint32_t (*As)[128][36] = (uint32_t(*)[128][36])smw;
    uint32_t (*Bs)[32][136] = (uint32_t(*)[32][136])(smw + 3 * 128 * 36);
    float* sSum = (float*)(smw + 3 * 128 * 36 + 3 * 32 * 136);
    float* sSq  = sSum + 128;

    const int tid = threadIdx.x;
    const int wid = tid >> 5, lane = tid & 31;
    const int wm = wid & 1, wn = wid >> 1;
    const int lr = lane >> 2, lc = lane & 3;

    const int s  = blockIdx.z;
    const int n0 = blockIdx.x * 128;
    const int m0 = blockIdx.y * 128;
    const int nvalid = min(128, Nfeat - n0);

    const float* Asl = A + (long long)s * aSliceStride;
    const float* Wsl = W + (long long)s * (long long)KB * Nw;

    if (tid < 128) { sSum[tid] = 0.f; sSq[tid] = 0.f; }

    auto issueStage = [&](int st) {
        const int buf = st % 3;
        const int k0 = st * 32;
#pragma unroll
        for (int p = 0; p < 4; p++) {
            int id = tid + p * 256;
            int row = id >> 3, q = id & 7;
            const float* src = Asl + (long long)(m0 + row) * 128 + k0 + q * 4;
            asm volatile("cp.async.ca.shared.global [%0], [%1], 16;"
                         :: "r"(smem_addr(&As[buf][row][q * 4])), "l"(src) : "memory");
        }
#pragma unroll
        for (int i = 0; i < 4; i++) {
            int kk = (tid >> 5) + i * 8;
            int n4 = (tid & 31) * 4;
            int kg = k0 + kk;
            int bytes = (kg < KB) ? 16 : 0;
            const float* src = Wsl + ((bytes > 0) ? ((long long)kg * Nw + n0 + n4) : 0LL);
            asm volatile("cp.async.ca.shared.global [%0], [%1], 16, %2;"
                         :: "r"(smem_addr(&Bs[buf][kk][n4])), "l"(src), "r"(bytes) : "memory");
        }
        asm volatile("cp.async.commit_group;" ::: "memory");
    };

    float acc[4][4][4];
#pragma unroll
    for (int mi = 0; mi < 4; mi++)
#pragma unroll
        for (int ni = 0; ni < 4; ni++)
#pragma unroll
            for (int q = 0; q < 4; q++) acc[mi][ni][q] = 0.f;

    // prologue: stages 0, 1 in flight
    issueStage(0);
    issueStage(1);

#pragma unroll
    for (int c = 0; c < 4; c++) {   // KDIM = 128 -> 4 chunks
        asm volatile("cp.async.wait_group 1;" ::: "memory");
        __syncthreads();
        if (c + 2 < 4) issueStage(c + 2);
        else asm volatile("cp.async.commit_group;" ::: "memory");  // keep group count uniform

        uint32_t (*Ab)[36] = As[c % 3];
        uint32_t (*Bb)[136] = Bs[c % 3];
#pragma unroll
        for (int ks = 0; ks < 4; ks++) {
            const int kb = ks * 8;
            uint32_t af[4][4];
#pragma unroll
            for (int mi = 0; mi < 4; mi++) {
                int r = wm * 64 + mi * 16 + lr;
                af[mi][0] = Ab[r][kb + lc];
                af[mi][1] = Ab[r + 8][kb + lc];
                af[mi][2] = Ab[r][kb + 4 + lc];
                af[mi][3] = Ab[r + 8][kb + 4 + lc];
            }
            uint32_t bf[4][2];
#pragma unroll
            for (int ni = 0; ni < 4; ni++) {
                int cc = wn * 32 + ni * 8 + lr;
                bf[ni][0] = Bb[kb + lc][cc];
                bf[ni][1] = Bb[kb + 4 + lc][cc];
            }
#pragma unroll
            for (int mi = 0; mi < 4; mi++)
#pragma unroll
                for (int ni = 0; ni < 4; ni++)
                    mma_tf32(acc[mi][ni], af[mi], bf[ni]);
        }
    }

    // ---- epilogue: bias, stats, store ----
    float bb[4][2];
#pragma unroll
    for (int ni = 0; ni < 4; ni++) {
        int cl = wn * 32 + ni * 8 + lc * 2;
        bb[ni][0] = (cl < nvalid) ? bias[(long long)s * Nfeat + n0 + cl] : 0.f;
        bb[ni][1] = (cl + 1 < nvalid) ? bias[(long long)s * Nfeat + n0 + cl + 1] : 0.f;
    }
    float cs[4][2] = {{0,0},{0,0},{0,0},{0,0}};
    float cq[4][2] = {{0,0},{0,0},{0,0},{0,0}};
#pragma unroll
    for (int mi = 0; mi < 4; mi++) {
        const int r0 = m0 + wm * 64 + mi * 16 + lr;
#pragma unroll
        for (int ni = 0; ni < 4; ni++) {
            const int cl = wn * 32 + ni * 8 + lc * 2;
            float v00 = acc[mi][ni][0] + bb[ni][0];
            float v01 = acc[mi][ni][1] + bb[ni][1];
            float v10 = acc[mi][ni][2] + bb[ni][0];
            float v11 = acc[mi][ni][3] + bb[ni][1];
            cs[ni][0] += v00 + v10;  cq[ni][0] += v00 * v00 + v10 * v10;
            cs[ni][1] += v01 + v11;  cq[ni][1] += v01 * v01 + v11 * v11;
            float* p0 = C + (long long)s * cSliceStride + (long long)r0 * ldC + n0 + cl;
            float* p1 = p0 + (long long)8 * ldC;
            if (cl + 1 < nvalid) {
                *(float2*)p0 = make_float2(v00, v01);
                *(float2*)p1 = make_float2(v10, v11);
            } else if (cl < nvalid) { *p0 = v00; *p1 = v10; }
        }
    }
#pragma unroll
    for (int ni = 0; ni < 4; ni++)
#pragma unroll
        for (int h = 0; h < 2; h++) {
            int cl = wn * 32 + ni * 8 + lc * 2 + h;
            if (cl < nvalid) { atomicAdd(&sSum[cl], cs[ni][h]); atomicAdd(&sSq[cl], cq[ni][h]); }
        }
    __syncthreads();
    if (tid < 128 && tid < nvalid) {
        atomicAdd(&g_stats[2 * statStage][s * Nfeat + n0 + tid], sSum[tid]);
        atomicAdd(&g_stats[2 * statStage + 1][s * Nfeat + n0 + tid], sSq[tid]);
    }
}

// ======================================================================
// general double-buffered GEMM (optional BN/ReLU pre-op, optional
// domain-selective store), as in round 6 with grid x = n-tile.
// ======================================================================
#define AS_WORDS (2 * 128 * 36)
#define BS_WORDS (2 * 32 * 136)
#define SMEM_BYTES ((AS_WORDS + BS_WORDS + 256 + 512) * 4)

template<bool AVEC, bool BVEC, bool PREOP, bool SELSTORE, int MINB>
__global__ void __launch_bounds__(256, MINB) gemm_tc(
    const float* __restrict__ A, long long aSliceStride, int ldA, int KDIM, int aKmax,
    const float* __restrict__ W, int Nw,
    const float* __restrict__ bias, int bnStage,
    float* __restrict__ C, long long cSliceStride, int ldC,
    int Nfeat, int statStage, const int* __restrict__ dom)
{
    extern __shared__ char dsm[];
    uint32_t* smw = (uint32_t*)dsm;
    uint32_t (*As)[128][36] = (uint32_t(*)[128][36])smw;
    uint32_t (*Bs)[32][136] = (uint32_t(*)[32][136])(smw + AS_WORDS);
    float* sBNa = (float*)(smw + AS_WORDS + BS_WORDS);
    float* sBNc = sBNa + 256;
    float* sSum = (float*)(smw + AS_WORDS + BS_WORDS + 512);
    float* sSq  = sSum + 128;

    const int tid = threadIdx.x;
    const int wid = tid >> 5, lane = tid & 31;
    const int wm = wid & 1, wn = wid >> 1;
    const int lr = lane >> 2, lc = lane & 3;

    const int s  = blockIdx.z;
    const int n0 = blockIdx.x * 128;
    const int m0 = blockIdx.y * 128;
    const int nvalid = min(128, Nfeat - n0);
    const int NC = (KDIM + 31) >> 5;

    const float* Asl = A + (long long)s * aSliceStride;
    const float* Wsl = W + (long long)s * (long long)KDIM * Nw;

    if (tid < 128) { sSum[tid] = 0.f; sSq[tid] = 0.f; }
    if (PREOP) {
        for (int i = tid; i < KDIM; i += 256) {
            sBNa[i] = g_bnA[bnStage][s * KDIM + i];
            sBNc[i] = g_bnC[bnStage][s * KDIM + i];
        }
    }

    float4 aReg[4];
    float  aS[16];
    float  bS[16];

    auto prefA = [&](int c) {
        const int k0 = c * 32;
        if (AVEC) {
#pragma unroll
            for (int p = 0; p < 4; p++) {
                int f = tid + p * 256;
                int row = f >> 3, q = f & 7;
                int kg = k0 + q * 4;
                if (kg < aKmax)
                    aReg[p] = *(const float4*)(Asl + (long long)(m0 + row) * ldA + kg);
                else
                    aReg[p] = make_float4(0.f, 0.f, 0.f, 0.f);
            }
        } else {
            const int col = tid & 31;
            const int kg = k0 + col;
            const bool kval = kg < KDIM;
#pragma unroll
            for (int i = 0; i < 16; i++) {
                int row = (tid >> 5) + i * 8;
                aS[i] = kval ? Asl[(long long)(m0 + row) * ldA + kg] : 0.f;
            }
        }
    };
    auto stsA = [&](int buf, int c) {
        const int k0 = c * 32;
        if (AVEC) {
#pragma unroll
            for (int p = 0; p < 4; p++) {
                int f = tid + p * 256;
                int row = f >> 3, q = f & 7;
                float4 v = aReg[p];
                if (PREOP) {
                    int kb = k0 + q * 4;
                    float4 a4 = *(const float4*)&sBNa[kb];
                    float4 c4 = *(const float4*)&sBNc[kb];
                    v.x = fmaxf(fmaf(v.x, a4.x, c4.x), 0.f);
                    v.y = fmaxf(fmaf(v.y, a4.y, c4.y), 0.f);
                    v.z = fmaxf(fmaf(v.z, a4.z, c4.z), 0.f);
                    v.w = fmaxf(fmaf(v.w, a4.w, c4.w), 0.f);
                }
                uint4 t;
                t.x = f2tf32(v.x); t.y = f2tf32(v.y);
                t.z = f2tf32(v.z); t.w = f2tf32(v.w);
                *(uint4*)&As[buf][row][q * 4] = t;
            }
        } else {
            const int col = tid & 31;
#pragma unroll
            for (int i = 0; i < 16; i++) {
                int row = (tid >> 5) + i * 8;
                As[buf][row][col] = f2tf32(aS[i]);
            }
        }
    };
    auto prefB = [&](int c, int buf) {
        const int k0 = c * 32;
        if (BVEC) {
#pragma unroll
            for (int i = 0; i < 4; i++) {
                int kk = (tid >> 5) + i * 8;
                int n4 = (tid & 31) * 4;
                int kg = k0 + kk;
                int rem = nvalid - n4;
                int bytes = (kg < KDIM) ? min(max(rem, 0) * 4, 16) : 0;
                const float* src = Wsl + ((bytes > 0) ? ((long long)kg * Nw + n0 + n4) : 0LL);
                asm volatile("cp.async.ca.shared.global [%0], [%1], 16, %2;"
                             :: "r"(smem_addr(&Bs[buf][kk][n4])), "l"(src), "r"(bytes) : "memory");
            }
            asm volatile("cp.async.commit_group;" ::: "memory");
        } else {
            const int n = tid & 127;
            const bool nok = n < nvalid;
#pragma unroll
            for (int i = 0; i < 16; i++) {
                int kk = (tid >> 7) + i * 2;
                int kg = k0 + kk;
                bS[i] = (kg < KDIM && nok) ? Wsl[(long long)kg * Nw + n0 + n] : 0.f;
            }
        }
    };
    auto stsB = [&](int buf) {
        if (!BVEC) {
            const int n = tid & 127;
#pragma unroll
            for (int i = 0; i < 16; i++) {
                int kk = (tid >> 7) + i * 2;
                Bs[buf][kk][n] = __float_as_uint(bS[i]);
            }
        }
    };

    float acc[4][4][4];
#pragma unroll
    for (int mi = 0; mi < 4; mi++)
#pragma unroll
        for (int ni = 0; ni < 4; ni++)
#pragma unroll
            for (int q = 0; q < 4; q++) acc[mi][ni][q] = 0.f;

    prefA(0);
    prefB(0, 0);
    if (PREOP) __syncthreads();
    stsA(0, 0);
    stsB(0);
    if (BVEC) asm volatile("cp.async.wait_group 0;" ::: "memory");
    __syncthreads();

    for (int c = 0; c < NC; c++) {
        const int cur = c & 1;
        const bool more = (c + 1) < NC;
        if (more) { prefA(c + 1); prefB(c + 1, cur ^ 1); }

        uint32_t (*Ab)[36] = As[cur];
        uint32_t (*Bb)[136] = Bs[cur];
#pragma unroll
        for (int ks = 0; ks < 4; ks++) {
            const int kb = ks * 8;
            uint32_t af[4][4];
#pragma unroll
            for (int mi = 0; mi < 4; mi++) {
                int r = wm * 64 + mi * 16 + lr;
                af[mi][0] = Ab[r][kb + lc];
                af[mi][1] = Ab[r + 8][kb + lc];
                af[mi][2] = Ab[r][kb + 4 + lc];
                af[mi][3] = Ab[r + 8][kb + 4 + lc];
            }
            uint32_t bf[4][2];
#pragma unroll
            for (int ni = 0; ni < 4; ni++) {
                int cc = wn * 32 + ni * 8 + lr;
                bf[ni][0] = Bb[kb + lc][cc];
                bf[ni][1] = Bb[kb + 4 + lc][cc];
            }
#pragma unroll
            for (int mi = 0; mi < 4; mi++)
#pragma unroll
                for (int ni = 0; ni < 4; ni++)
                    mma_tf32(acc[mi][ni], af[mi], bf[ni]);
        }

        if (more) { stsA(cur ^ 1, c + 1); stsB(cur ^ 1); }
        if (BVEC) asm volatile("cp.async.wait_group 0;" ::: "memory");
        __syncthreads();
    }

    // ---- epilogue ----
    float bb[4][2];
#pragma unroll
    for (int ni = 0; ni < 4; ni++) {
        int cl = wn * 32 + ni * 8 + lc * 2;
        bb[ni][0] = (cl < nvalid) ? bias[(long long)s * Nfeat + n0 + cl] : 0.f;
        bb[ni][1] = (cl + 1 < nvalid) ? bias[(long long)s * Nfeat + n0 + cl + 1] : 0.f;
    }
    float cs[4][2] = {{0,0},{0,0},{0,0},{0,0}};
    float cq[4][2] = {{0,0},{0,0},{0,0},{0,0}};

#pragma unroll
    for (int mi = 0; mi < 4; mi++) {
        const int r0 = m0 + wm * 64 + mi * 16 + lr;
        bool st0 = true, st1 = true;
        if (SELSTORE) {
            int d0 = g_domIsI64 ? (int)(((const long long*)dom)[r0])     : dom[r0];
            int d1 = g_domIsI64 ? (int)(((const long long*)dom)[r0 + 8]) : dom[r0 + 8];
            st0 = (d0 == s); st1 = (d1 == s);
        }
#pragma unroll
        for (int ni = 0; ni < 4; ni++) {
            const int cl = wn * 32 + ni * 8 + lc * 2;
            float v00 = acc[mi][ni][0] + bb[ni][0];
            float v01 = acc[mi][ni][1] + bb[ni][1];
            float v10 = acc[mi][ni][2] + bb[ni][0];
            float v11 = acc[mi][ni][3] + bb[ni][1];
            cs[ni][0] += v00 + v10;  cq[ni][0] += v00 * v00 + v10 * v10;
            cs[ni][1] += v01 + v11;  cq[ni][1] += v01 * v01 + v11 * v11;
            float* p0 = C + (long long)s * cSliceStride + (long long)r0 * ldC + n0 + cl;
            float* p1 = p0 + (long long)8 * ldC;
            if (cl + 1 < nvalid) {
                if (st0) *(float2*)p0 = make_float2(v00, v01);
                if (st1) *(float2*)p1 = make_float2(v10, v11);
            } else if (cl < nvalid) {
                if (st0) *p0 = v00;
                if (st1) *p1 = v10;
            }
        }
    }
#pragma unroll
    for (int ni = 0; ni < 4; ni++)
#pragma unroll
        for (int h = 0; h < 2; h++) {
            int cl = wn * 32 + ni * 8 + lc * 2 + h;
            if (cl < nvalid) { atomicAdd(&sSum[cl], cs[ni][h]); atomicAdd(&sSq[cl], cq[ni][h]); }
        }
    __syncthreads();
    if (tid < 128 && tid < nvalid) {
        atomicAdd(&g_stats[2 * statStage][s * Nfeat + n0 + tid], sSum[tid]);
        atomicAdd(&g_stats[2 * statStage + 1][s * Nfeat + n0 + tid], sSq[tid]);
    }
}

// ---------------- small kernels ----------------
__global__ void zero_stats_kernel() {
    int i = blockIdx.x * 1024 + threadIdx.x;
    if (i < 8 * 2048) ((float*)g_stats)[i] = 0.f;
}

__global__ void finalize_kernel(int stage, const float* __restrict__ gamma,
                                const float* __restrict__ beta, int n, float invB) {
    int i = blockIdx.x * blockDim.x + threadIdx.x;
    if (i < n) {
        float m = g_stats[2 * stage][i] * invB;
        float v = g_stats[2 * stage + 1][i] * invB - m * m;
        float sc = gamma[i] / sqrtf(v + 1e-5f);
        g_bnA[stage][i] = sc;
        g_bnC[stage][i] = beta[i] - m * sc;
    }
}

__global__ void probe_domain_kernel(const int* __restrict__ dom) {
    const long long* d64 = (const long long*)dom;
    bool ok = true;
    for (int i = 0; i < 64; i++) {
        long long v = d64[i];
        if (v < 0 || v >= 8) ok = false;
    }
    g_domIsI64 = ok ? 1 : 0;
}

// gates(softmax over E) + BN/ReLU(fea) + expert mixture -> task[d][b][c] (stride 128, pad zeroed)
__global__ void gates_task_kernel(const float* __restrict__ emb,
                                  const float* __restrict__ Wg,
                                  const float* __restrict__ bg,
                                  const float* __restrict__ fea_pre,
                                  float* __restrict__ task, int B) {
    __shared__ float s_emb[113];
    __shared__ float s_g[8][4];
    const int b = blockIdx.x;
    const int tid = threadIdx.x;
    if (tid < 113) s_emb[tid] = emb[(long long)b * 113 + tid];
    __syncthreads();
    if (tid < 32) {
        int d = tid >> 2, e = tid & 3;
        float acc = bg[d * 4 + e];
        const float* w = Wg + d * 113 * 4 + e;
        for (int i = 0; i < 113; i++) acc = fmaf(s_emb[i], w[i * 4], acc);
        s_g[d][e] = acc;
    }
    __syncthreads();
    if (tid < 8) {
        float g0 = s_g[tid][0], g1 = s_g[tid][1], g2 = s_g[tid][2], g3 = s_g[tid][3];
        float m = fmaxf(fmaxf(g0, g1), fmaxf(g2, g3));
        float e0 = expf(g0 - m), e1 = expf(g1 - m), e2 = expf(g2 - m), e3 = expf(g3 - m);
        float inv = 1.f / (e0 + e1 + e2 + e3);
        s_g[tid][0] = e0 * inv; s_g[tid][1] = e1 * inv;
        s_g[tid][2] = e2 * inv; s_g[tid][3] = e3 * inv;
    }
    __syncthreads();
    if (tid < 113) {
        float fe[4];
#pragma unroll
        for (int e = 0; e < 4; e++) {
            float x = fea_pre[((long long)e * B + b) * 128 + tid];
            fe[e] = fmaxf(fmaf(x, g_bnA[1][e * 113 + tid], g_bnC[1][e * 113 + tid]), 0.f);
        }
#pragma unroll
        for (int d = 0; d < 8; d++) {
            float t = s_g[d][0] * fe[0] + s_g[d][1] * fe[1] + s_g[d][2] * fe[2] + s_g[d][3] * fe[3];
            task[((long long)d * B + b) * 128 + tid] = t;
        }
    } else {
#pragma unroll
        for (int d = 0; d < 8; d++)
            task[((long long)d * B + b) * 128 + tid] = 0.f;
    }
}

// final: per b, pick domain tower, BN+ReLU on t2, dot with Wt3, sigmoid
__global__ void final_kernel(const float* __restrict__ t2,
                             const float* __restrict__ Wt3,
                             const float* __restrict__ bt3,
                             const int* __restrict__ dom,
                             float* __restrict__ out, int B) {
    int gid = blockIdx.x * blockDim.x + threadIdx.x;
    int b = gid >> 5, lane = gid & 31;
    if (b >= B) return;
    int d = g_domIsI64 ? (int)(((const long long*)dom)[b]) : dom[b];
    float4 x  = reinterpret_cast<const float4*>(t2 + ((long long)d * B + b) * 128)[lane];
    float4 aa = *reinterpret_cast<const float4*>(&g_bnA[3][d * 128 + lane * 4]);
    float4 cc = *reinterpret_cast<const float4*>(&g_bnC[3][d * 128 + lane * 4]);
    float4 w  = reinterpret_cast<const float4*>(Wt3 + d * 128)[lane];
    float s = fmaxf(fmaf(x.x, aa.x, cc.x), 0.f) * w.x
            + fmaxf(fmaf(x.y, aa.y, cc.y), 0.f) * w.y
            + fmaxf(fmaf(x.z, aa.z, cc.z), 0.f) * w.z
            + fmaxf(fmaf(x.w, aa.w, cc.w), 0.f) * w.w;
#pragma unroll
    for (int o = 16; o; o >>= 1) s += __shfl_xor_sync(0xffffffffu, s, o);
    if (lane == 0) out[b] = 1.f / (1.f + expf(-(s + bt3[d])));
}

// ---------------- host ----------------
extern "C" void kernel_launch(void* const* d_in, const int* in_sizes, int n_in,
                              void* d_out, int out_size) {
    const int B = 131072;
    int domIdx = -1;
    for (int i = 0; i < n_in; i++)
        if (in_sizes[i] == B) { domIdx = i; break; }

    const float* ptrs[21];
    int pi = 0;
    for (int i = 0; i < n_in && pi < 21; i++) {
        if (i == domIdx) continue;
        ptrs[pi++] = (const float*)d_in[i];
    }
    const float* emb = ptrs[0];
    const float* We1 = ptrs[1],  *be1 = ptrs[2],  *eg1 = ptrs[3],  *eb1 = ptrs[4];
    const float* We2 = ptrs[5],  *be2 = ptrs[6],  *eg2 = ptrs[7],  *eb2 = ptrs[8];
    const float* Wg  = ptrs[9],  *bg  = ptrs[10];
    const float* Wt1 = ptrs[11], *bt1 = ptrs[12], *tg1 = ptrs[13], *tb1 = ptrs[14];
    const float* Wt2 = ptrs[15], *bt2 = ptrs[16], *tg2 = ptrs[17], *tb2 = ptrs[18];
    const float* Wt3 = ptrs[19], *bt3 = ptrs[20];
    const int* dom = (const int*)d_in[domIdx];
    float* out = (float*)d_out;

    float *p_h1, *p_fea, *p_task, *p_t1;
    cudaGetSymbolAddress((void**)&p_h1,  g_h1);
    cudaGetSymbolAddress((void**)&p_fea, g_fea);
    cudaGetSymbolAddress((void**)&p_task, g_task);
    cudaGetSymbolAddress((void**)&p_t1,  g_t1);

    cudaFuncSetAttribute(gemm_tc<false, true,  false, false, 2>, cudaFuncAttributeMaxDynamicSharedMemorySize, SMEM_BYTES);
    cudaFuncSetAttribute(gemm_tc<true,  false, true,  false, 1>, cudaFuncAttributeMaxDynamicSharedMemorySize, SMEM_BYTES);
    cudaFuncSetAttribute(gemm_tc<true,  true,  true,  true,  2>, cudaFuncAttributeMaxDynamicSharedMemorySize, SMEM_BYTES);
    cudaFuncSetAttribute(gemm_async, cudaFuncAttributeMaxDynamicSharedMemorySize, ASY_BYTES);

    const float invB = 1.f / (float)B;

    probe_domain_kernel<<<1, 1>>>(dom);
    zero_stats_kernel<<<16, 1024>>>();

    // expert layer 1: emb [B,113] x We1 [113,256] per expert -> h1 (stride 256)
    gemm_tc<false, true, false, false, 2><<<dim3(2, B / 128, 4), 256, SMEM_BYTES>>>(
        emb, 0LL, 113, 113, 113, We1, 256, be1, 0, p_h1, (long long)B * 256, 256, 256, 0, nullptr);
    finalize_kernel<<<4, 256>>>(0, eg1, eb1, 4 * 256, invB);

    // expert layer 2: BN+ReLU(h1) [B,256] x We2 [256,113] -> fea (stride 128, 113 valid)
    gemm_tc<true, false, true, false, 1><<<dim3(1, B / 128, 4), 256, SMEM_BYTES>>>(
        p_h1, (long long)B * 256, 256, 256, 256, We2, 113, be2, 0, p_fea, (long long)B * 128, 128, 113, 1, nullptr);
    finalize_kernel<<<2, 256>>>(1, eg2, eb2, 4 * 113, invB);

    // gates + mixture -> task[d][b][c] (stride 128, pad zeroed)
    gates_task_kernel<<<B, 128>>>(emb, Wg, bg, p_fea, p_task, B);

    // tower layer 1 (async GEMM): task [B,128 pad] x Wt1 [113,256] per domain -> t1
    gemm_async<<<dim3(2, B / 128, 8), 256, ASY_BYTES>>>(
        p_task, (long long)B * 128, Wt1, 256, 113, bt1, p_t1, (long long)B * 256, 256, 256, 2);
    finalize_kernel<<<8, 256>>>(2, tg1, tb1, 8 * 256, invB);

    // tower layer 2: BN+ReLU(t1) [B,256] x Wt2 [256,128] per domain -> t2 (reuses g_h1),
    // storing only rows whose domain matches (stats still cover all rows)
    gemm_tc<true, true, true, true, 2><<<dim3(1, B / 128, 8), 256, SMEM_BYTES>>>(
        p_t1, (long long)B * 256, 256, 256, 256, Wt2, 128, bt2, 2, p_h1, (long long)B * 128, 128, 128, 3, dom);
    finalize_kernel<<<4, 256>>>(3, tg2, tb2, 8 * 128, invB);

    // final: gather domain, BN+ReLU, dot Wt3, sigmoid
    final_kernel<<<(B * 32) / 256, 256>>>(p_h1, Wt3, bt3, dom, out, B);
}